// round 14
// baseline (speedup 1.0000x reference)
#include <cuda_runtime.h>
#include <cuda_bf16.h>
#include <math.h>
#include <stdint.h>

#define D_MODEL 256
#define NHEAD   8
#define HEAD_DIM 32
#define B_SZ    4
#define N_SZ    256

// ---------------- device scratch ----------------
__device__ float g_Wt[D_MODEL * D_MODEL];
__device__ float g_node_p[B_SZ * N_SZ * D_MODEL];
__device__ float g_out0[B_SZ * N_SZ * D_MODEL];
// W bf16 splits: 8 K-chunks x 2 d-halves x [128 n][32 k] bf16, 64B rows, SW64 (8KB blocks)
__device__ __align__(128) unsigned char g_WB_hi[131072];
__device__ __align__(128) unsigned char g_WB_lo[131072];

__device__ __forceinline__ uint32_t smem_u32(const void* p) {
    uint32_t a;
    asm("{ .reg .u64 t; cvta.to.shared.u64 t, %1; cvt.u32.u64 %0, t; }" : "=r"(a) : "l"(p));
    return a;
}

__device__ __forceinline__ void ldsm_x4(uint32_t r[4], uint32_t addr) {
    asm volatile("ldmatrix.sync.aligned.m8n8.x4.shared.b16 {%0,%1,%2,%3}, [%4];"
                 : "=r"(r[0]), "=r"(r[1]), "=r"(r[2]), "=r"(r[3]) : "r"(addr));
}

__device__ __forceinline__ void mma_bf16(float c[4], const uint32_t a[4], const uint32_t b[2]) {
    asm volatile(
        "mma.sync.aligned.m16n8k16.row.col.f32.bf16.bf16.f32 "
        "{%0,%1,%2,%3}, {%4,%5,%6,%7}, {%8,%9}, {%0,%1,%2,%3};"
        : "+f"(c[0]), "+f"(c[1]), "+f"(c[2]), "+f"(c[3])
        : "r"(a[0]), "r"(a[1]), "r"(a[2]), "r"(a[3]), "r"(b[0]), "r"(b[1]));
}

#define MBAR_INIT(mbar, cnt) \
    asm volatile("mbarrier.init.shared.b64 [%0], %1;" :: "r"((uint32_t)(mbar)), "r"((uint32_t)(cnt)) : "memory")
#define MBAR_EXPECT_TX(mbar, tx) \
    asm volatile("mbarrier.arrive.expect_tx.shared.b64 _, [%0], %1;" :: "r"((uint32_t)(mbar)), "r"((uint32_t)(tx)) : "memory")
#define MBAR_WAIT(mbar, parity) do {                                          \
    uint32_t _m = (uint32_t)(mbar); uint32_t _p = (uint32_t)(parity);         \
    asm volatile(                                                             \
        "{\n\t.reg .pred P1;\n\t"                                             \
        "WAIT_LOOP_%=:\n\t"                                                   \
        "mbarrier.try_wait.parity.acquire.cta.shared::cta.b64 P1, [%0], %1, 0x989680;\n\t" \
        "@P1 bra.uni WAIT_DONE_%=;\n\t"                                       \
        "bra.uni WAIT_LOOP_%=;\n\t"                                           \
        "WAIT_DONE_%=:\n\t}"                                                  \
        :: "r"(_m), "r"(_p) : "memory");                                      \
} while (0)
#define BULK_G2S(dst, src, bytes, mbar) \
    asm volatile("cp.async.bulk.shared::cta.global.mbarrier::complete_tx::bytes [%0], [%1], %2, [%3];" \
                 :: "r"((uint32_t)(dst)), "l"(src), "r"((uint32_t)(bytes)), "r"((uint32_t)(mbar)) : "memory")

// ---------------- prep kernels ----------------
__global__ void transpose_kernel(const float* __restrict__ W) {
    int o = blockIdx.x * 256 + threadIdx.x;  // o = k*256 + d
    int k = o >> 8, d = o & 255;
    g_Wt[o] = W[d * 256 + k];
}

// 8 chunks x 2 d-halves x [128 n][32 k], 64B rows, SW64
__global__ void wprep_kernel(const float* __restrict__ W) {
    int idx = blockIdx.x * 256 + threadIdx.x;  // d*256 + k
    int d = idx >> 8, k = idx & 255;
    float w = W[idx];
    __nv_bfloat16 h = __float2bfloat16_rn(w);
    float r = w - __bfloat162float(h);
    __nv_bfloat16 l = __float2bfloat16_rn(r);
    int chunk = k >> 5, kc = k & 31;
    int dh = d >> 7, dl = d & 127;
    int off = dl * 64 + kc * 2;
    int sw = off ^ ((off >> 3) & 0x30);      // SW64
    int pos = chunk * 16384 + dh * 8192 + sw;
    *(unsigned short*)(g_WB_hi + pos) = __bfloat16_as_ushort(h);
    *(unsigned short*)(g_WB_lo + pos) = __bfloat16_as_ushort(l);
}

// ---------------- high-occupancy projections (R12 exact) ----------------
__global__ void __launch_bounds__(256, 6)
proj_nodes_simple(const float* __restrict__ A, const float* __restrict__ bias) {
    __shared__ float As[4][256];
    const int tid = threadIdx.x;
    const int r0 = blockIdx.x * 4;

#pragma unroll
    for (int q = 0; q < 4; q++)
        As[q][tid] = A[(size_t)(r0 + q) * 256 + tid];
    __syncthreads();

    float a0 = 0.0f, a1 = 0.0f, a2 = 0.0f, a3 = 0.0f;
#pragma unroll 8
    for (int k = 0; k < 256; k++) {
        float wv = g_Wt[k * 256 + tid];
        a0 = fmaf(As[0][k], wv, a0);
        a1 = fmaf(As[1][k], wv, a1);
        a2 = fmaf(As[2][k], wv, a2);
        a3 = fmaf(As[3][k], wv, a3);
    }
    float bv = bias[tid];
    g_node_p[(size_t)(r0 + 0) * 256 + tid] = a0 + bv;
    g_node_p[(size_t)(r0 + 1) * 256 + tid] = a1 + bv;
    g_node_p[(size_t)(r0 + 2) * 256 + tid] = a2 + bv;
    g_node_p[(size_t)(r0 + 3) * 256 + tid] = a3 + bv;
}

__global__ void __launch_bounds__(256, 6)
proj_final_simple(const float* __restrict__ bias, float* __restrict__ C) {
    __shared__ float As[4][256];
    const int tid = threadIdx.x;
    const int r0 = blockIdx.x * 4;

#pragma unroll
    for (int q = 0; q < 4; q++)
        As[q][tid] = g_out0[(size_t)(r0 + q) * 256 + tid];
    __syncthreads();

    float a0 = 0.0f, a1 = 0.0f, a2 = 0.0f, a3 = 0.0f;
#pragma unroll 8
    for (int k = 0; k < 256; k++) {
        float wv = g_Wt[k * 256 + tid];
        a0 = fmaf(As[0][k], wv, a0);
        a1 = fmaf(As[1][k], wv, a1);
        a2 = fmaf(As[2][k], wv, a2);
        a3 = fmaf(As[3][k], wv, a3);
    }
    float bv = bias[tid];
    C[(size_t)(r0 + 0) * 256 + tid] = a0 + bv;
    C[(size_t)(r0 + 1) * 256 + tid] = a1 + bv;
    C[(size_t)(r0 + 2) * 256 + tid] = a2 + bv;
    C[(size_t)(r0 + 3) * 256 + tid] = a3 + bv;
}

// ---------------- edge projection + scores: d-split, 64j x 128d per CTA ----------------
// SMEM: A slots: 2 x (4KB hi + 4KB lo)  @ 0      (16KB)
//       W slots: 2 x (8KB hi + 8KB lo)  @ 16384  (32KB)
// Total 48KB -> 3 CTAs/SM (regs permitting).
#define SM_A   0
#define SM_W   16384
#define SM_DYN 49152
#define NTHR   256

// convert one float4 of A-chunk data (64 rows x 32 k, 64B rows, SW64)
__device__ __forceinline__ void cvt_store_a(char* sm, int slot, int flat, float4 v) {
    __nv_bfloat16 hx = __float2bfloat16_rn(v.x);
    __nv_bfloat16 hy = __float2bfloat16_rn(v.y);
    __nv_bfloat16 hz = __float2bfloat16_rn(v.z);
    __nv_bfloat16 hw = __float2bfloat16_rn(v.w);
    __nv_bfloat16 lx = __float2bfloat16_rn(v.x - __bfloat162float(hx));
    __nv_bfloat16 ly = __float2bfloat16_rn(v.y - __bfloat162float(hy));
    __nv_bfloat16 lz = __float2bfloat16_rn(v.z - __bfloat162float(hz));
    __nv_bfloat16 lw = __float2bfloat16_rn(v.w - __bfloat162float(hw));
    uint2 hi2, lo2;
    hi2.x = (uint32_t)__bfloat16_as_ushort(hx) | ((uint32_t)__bfloat16_as_ushort(hy) << 16);
    hi2.y = (uint32_t)__bfloat16_as_ushort(hz) | ((uint32_t)__bfloat16_as_ushort(hw) << 16);
    lo2.x = (uint32_t)__bfloat16_as_ushort(lx) | ((uint32_t)__bfloat16_as_ushort(ly) << 16);
    lo2.y = (uint32_t)__bfloat16_as_ushort(lz) | ((uint32_t)__bfloat16_as_ushort(lw) << 16);
    int row = flat >> 3, c4 = flat & 7;      // 8 float4 per 32-k row
    int off = row * 64 + c4 * 8;
    int sw = off ^ ((off >> 3) & 0x30);      // SW64
    char* base = sm + SM_A + slot * 8192;
    *(uint2*)(base + sw) = hi2;
    *(uint2*)(base + 4096 + sw) = lo2;
}

__global__ void __launch_bounds__(NTHR, 3)
edge_score_mma(const float* __restrict__ edges, const float* __restrict__ bias,
               float* __restrict__ scores) {
    extern __shared__ char sm[];
    __shared__ __align__(8) unsigned long long mbarr[2];
    const uint32_t smb = smem_u32(sm);
    const uint32_t mb0 = smem_u32(&mbarr[0]);
    const int tid = threadIdx.x, wid = tid >> 5, lane = tid & 31;
    const int jt = blockIdx.x & 3, dh = blockIdx.x >> 2;
    const int i = blockIdx.y, b = blockIdx.z;
    const int wm = (wid >> 2) * 32;          // 2 m-groups of 32 rows
    const int wn = (wid & 3) * 32;           // 4 n-groups of 32 cols = one head each

    const float* A = edges + ((((size_t)b * N_SZ + i) * N_SZ) + (size_t)jt * 64) * D_MODEL;
    const unsigned long long gwh = (unsigned long long)__cvta_generic_to_global(g_WB_hi) + dh * 8192;
    const unsigned long long gwl = (unsigned long long)__cvta_generic_to_global(g_WB_lo) + dh * 8192;

    if (tid == 0) { MBAR_INIT(mb0, 1); MBAR_INIT(mb0 + 8, 1); }
    __syncthreads();

    // ---- prologue: W chunk 0 (bulk, slot 0) + A chunk 0 (convert, slot 0) ----
    if (tid == 0) {
        MBAR_EXPECT_TX(mb0, 16384);
        BULK_G2S(smb + SM_W, gwh, 8192, mb0);
        BULK_G2S(smb + SM_W + 8192, gwl, 8192, mb0);
    }
#pragma unroll
    for (int q = 0; q < 2; q++) {
        int flat = q * NTHR + tid;           // 512 float4 per chunk
        float4 v = *(const float4*)(A + (size_t)(flat >> 3) * 256 + (flat & 7) * 4);
        cvt_store_a(sm, 0, flat, v);
    }
    __syncthreads();

    float acc[2][4][4];
#pragma unroll
    for (int mf = 0; mf < 2; mf++)
#pragma unroll
        for (int nf = 0; nf < 4; nf++)
#pragma unroll
            for (int c = 0; c < 4; c++) acc[mf][nf][c] = 0.0f;

    uint32_t apre[2], axor[2];
#pragma unroll
    for (int mf = 0; mf < 2; mf++) {
        int row = wm + mf * 16 + (lane & 15);
        apre[mf] = row * 64;
        axor[mf] = (row & 6) << 3;           // SW64
    }
    const int koffA = (lane >> 4) * 8;
    uint32_t bpre[2], bxor[2];
#pragma unroll
    for (int gb = 0; gb < 2; gb++) {
        int n = wn + gb * 16 + (((lane >> 3) >= 2) ? 8 : 0) + (lane & 7);
        bpre[gb] = n * 64;
        bxor[gb] = (n & 6) << 3;             // SW64
    }
    const int kcB = ((lane >> 3) & 1) * 8;

#pragma unroll 1
    for (int ch = 0; ch < 8; ch++) {
        const int cur = ch & 1, nxt = cur ^ 1;
        if (ch < 7 && tid == 0) {
            MBAR_EXPECT_TX(mb0 + 8 * nxt, 16384);
            BULK_G2S(smb + SM_W + nxt * 16384, gwh + (ch + 1) * 16384, 8192, mb0 + 8 * nxt);
            BULK_G2S(smb + SM_W + nxt * 16384 + 8192, gwl + (ch + 1) * 16384, 8192, mb0 + 8 * nxt);
        }
        MBAR_WAIT(mb0 + 8 * cur, (ch >> 1) & 1);

        const uint32_t abase = smb + SM_A + cur * 8192;
        const uint32_t wbase = smb + SM_W + cur * 16384;

#pragma unroll
        for (int ks = 0; ks < 2; ks++) {
            float4 v0;
            int f0 = ks * NTHR + tid;
            if (ch < 7)
                v0 = *(const float4*)(A + (ch + 1) * 32 + (size_t)(f0 >> 3) * 256 + (f0 & 7) * 4);

            const uint32_t kg2 = (uint32_t)((ks * 16 + koffA) * 2);
            uint32_t ah[2][4], al[2][4];
#pragma unroll
            for (int mf = 0; mf < 2; mf++) {
                uint32_t ad = abase + apre[mf] + (kg2 ^ axor[mf]);
                ldsm_x4(ah[mf], ad);
                ldsm_x4(al[mf], ad + 4096);
            }
            const uint32_t kc2 = (uint32_t)((ks * 16 + kcB) * 2);
#pragma unroll
            for (int gb = 0; gb < 2; gb++) {
                uint32_t bh[4], bl[4];
                uint32_t bd = wbase + bpre[gb] + (kc2 ^ bxor[gb]);
                ldsm_x4(bh, bd);
                ldsm_x4(bl, bd + 8192);
#pragma unroll
                for (int mf = 0; mf < 2; mf++)
#pragma unroll
                    for (int s2 = 0; s2 < 2; s2++)
                        mma_bf16(acc[mf][gb * 2 + s2], ah[mf], &bh[s2 * 2]);
#pragma unroll
                for (int mf = 0; mf < 2; mf++)
#pragma unroll
                    for (int s2 = 0; s2 < 2; s2++)
                        mma_bf16(acc[mf][gb * 2 + s2], ah[mf], &bl[s2 * 2]);
#pragma unroll
                for (int mf = 0; mf < 2; mf++)
#pragma unroll
                    for (int s2 = 0; s2 < 2; s2++)
                        mma_bf16(acc[mf][gb * 2 + s2], al[mf], &bh[s2 * 2]);
            }

            if (ch < 7) cvt_store_a(sm, nxt, f0, v0);
        }
        __syncthreads();
    }

    // ---- epilogue: stage npj half-slice (64 rows x 128 d, stride 132) ----
    {
        float* nps = (float*)sm;
        const float* src = g_node_p + ((size_t)b * N_SZ + jt * 64) * 256 + dh * 128;
        int row = tid >> 2, lq = tid & 3;
        const float4* s4 = (const float4*)(src + (size_t)row * 256) + lq * 8;
        float4* d4 = (float4*)(nps + row * 132) + lq * 8;
#pragma unroll
        for (int q = 0; q < 8; q++) d4[q] = s4[q];
    }
    __syncthreads();

    // per-thread bias/np_i constants for this warp's head (8 cols/thread)
    float pb[8], p1[8];
    {
        const float* npi = g_node_p + ((size_t)b * N_SZ + i) * 256;
#pragma unroll
        for (int nf = 0; nf < 4; nf++)
#pragma unroll
            for (int v2 = 0; v2 < 2; v2++) {
                int idx = nf * 2 + v2;
                int d = dh * 128 + wn + nf * 8 + (lane & 3) * 2 + v2;
                float bv = bias[d];
                pb[idx] = bv;
                p1[idx] = bv + npi[d];
            }
    }

    const int hg = dh * 4 + (wid & 3);
    const float* nps = (const float*)sm;
#pragma unroll
    for (int mf = 0; mf < 2; mf++) {
#pragma unroll
        for (int half = 0; half < 2; half++) {
            int r = wm + mf * 16 + (lane >> 2) + half * 8;
            const float* nj = nps + r * 132 + wn;
            float s = 0.0f;
#pragma unroll
            for (int nf = 0; nf < 4; nf++)
#pragma unroll
                for (int v2 = 0; v2 < 2; v2++) {
                    int idx = nf * 2 + v2;
                    float a = acc[mf][nf][half * 2 + v2];
                    float njv = nj[nf * 8 + (lane & 3) * 2 + v2];
                    s += (a + p1[idx]) * (a + pb[idx] + njv);
                }
            s += __shfl_xor_sync(0xffffffffu, s, 1);
            s += __shfl_xor_sync(0xffffffffu, s, 2);
            if ((lane & 3) == 0) {
                scores[((((size_t)b * NHEAD + hg) * N_SZ + i) << 8) + jt * 64 + r] =
                    10.0f * tanhf(s * 0.17677669529663687f);
            }
        }
    }
}

// ---------------- softmax + AV (R6 exact) ----------------
__global__ void softmax_av_kernel(float* __restrict__ attn) {
    const int i = blockIdx.x, h = blockIdx.y, b = blockIdx.z;
    const int tid = threadIdx.x;
    float* row = attn + ((((size_t)(b * NHEAD + h) * N_SZ) + i) << 8);

    __shared__ float sh[16];
    __shared__ float ps[256];
    __shared__ float red[8][33];

    float s = row[tid];
    float m = s;
#pragma unroll
    for (int off = 16; off > 0; off >>= 1)
        m = fmaxf(m, __shfl_xor_sync(0xffffffffu, m, off));
    if ((tid & 31) == 0) sh[tid >> 5] = m;
    __syncthreads();
    float bm = sh[0];
#pragma unroll
    for (int g = 1; g < 8; g++) bm = fmaxf(bm, sh[g]);

    float p = __expf(s - bm);
    float t = p;
#pragma unroll
    for (int off = 16; off > 0; off >>= 1)
        t += __shfl_xor_sync(0xffffffffu, t, off);
    if ((tid & 31) == 0) sh[8 + (tid >> 5)] = t;
    __syncthreads();
    float sum = 0.0f;
#pragma unroll
    for (int g = 0; g < 8; g++) sum += sh[8 + g];

    float a = p * (1.0f / sum);
    row[tid] = a;
    ps[tid] = a;
    __syncthreads();

    const int d = tid & 31, g = tid >> 5;
    const float* np = g_node_p + (size_t)b * N_SZ * D_MODEL + h * 32 + d;
    float acc = 0.0f;
#pragma unroll
    for (int jj = 0; jj < 32; jj++) {
        int j = g * 32 + jj;
        acc = fmaf(ps[j], np[(size_t)j * 256], acc);
    }
    red[g][d] = acc;
    __syncthreads();
    if (tid < 32) {
        float o = 0.0f;
#pragma unroll
        for (int g2 = 0; g2 < 8; g2++) o += red[g2][tid];
        g_out0[((size_t)(b * N_SZ + i)) * D_MODEL + h * 32 + tid] = o;
    }
}

// ---------------- launch ----------------
extern "C" void kernel_launch(void* const* d_in, const int* in_sizes, int n_in,
                              void* d_out, int out_size) {
    const float* nodes = (const float*)d_in[0];
    const float* edges = (const float*)d_in[1];
    const float* W     = (const float*)d_in[2];
    const float* bias  = (const float*)d_in[3];

    float* out  = (float*)d_out;
    float* attn = out + B_SZ * N_SZ * D_MODEL;

    cudaFuncSetAttribute(edge_score_mma, cudaFuncAttributeMaxDynamicSharedMemorySize, SM_DYN);

    transpose_kernel<<<256, 256>>>(W);                          // 0
    wprep_kernel<<<256, 256>>>(W);                              // 1
    proj_nodes_simple<<<256, 256>>>(nodes, bias);               // 2
    dim3 g2(8, N_SZ, B_SZ);
    edge_score_mma<<<g2, NTHR, SM_DYN>>>(edges, bias, attn);    // 3 (profiled)
    dim3 g3(N_SZ, NHEAD, B_SZ);
    softmax_av_kernel<<<g3, 256>>>(attn);                       // 4
    proj_final_simple<<<256, 256>>>(bias, out);                 // 5
}

// round 15
// speedup vs baseline: 1.0683x; 1.0683x over previous
#include <cuda_runtime.h>
#include <cuda_bf16.h>
#include <math.h>
#include <stdint.h>

#define D_MODEL 256
#define NHEAD   8
#define HEAD_DIM 32
#define B_SZ    4
#define N_SZ    256

// ---------------- device scratch ----------------
__device__ float g_Wt[D_MODEL * D_MODEL];
__device__ float g_node_p[B_SZ * N_SZ * D_MODEL];
__device__ float g_out0[B_SZ * N_SZ * D_MODEL];
// W bf16 splits, 8 K-chunks of [256 n][32 k] bf16, 64B rows, SW64 swizzle (16KB/chunk)
__device__ __align__(128) unsigned char g_WB_hi[131072];
__device__ __align__(128) unsigned char g_WB_lo[131072];

__device__ __forceinline__ uint32_t smem_u32(const void* p) {
    uint32_t a;
    asm("{ .reg .u64 t; cvta.to.shared.u64 t, %1; cvt.u32.u64 %0, t; }" : "=r"(a) : "l"(p));
    return a;
}

__device__ __forceinline__ void ldsm_x4(uint32_t r[4], uint32_t addr) {
    asm volatile("ldmatrix.sync.aligned.m8n8.x4.shared.b16 {%0,%1,%2,%3}, [%4];"
                 : "=r"(r[0]), "=r"(r[1]), "=r"(r[2]), "=r"(r[3]) : "r"(addr));
}

__device__ __forceinline__ void mma_bf16(float c[4], const uint32_t a[4], const uint32_t b[2]) {
    asm volatile(
        "mma.sync.aligned.m16n8k16.row.col.f32.bf16.bf16.f32 "
        "{%0,%1,%2,%3}, {%4,%5,%6,%7}, {%8,%9}, {%0,%1,%2,%3};"
        : "+f"(c[0]), "+f"(c[1]), "+f"(c[2]), "+f"(c[3])
        : "r"(a[0]), "r"(a[1]), "r"(a[2]), "r"(a[3]), "r"(b[0]), "r"(b[1]));
}

#define MBAR_INIT(mbar, cnt) \
    asm volatile("mbarrier.init.shared.b64 [%0], %1;" :: "r"((uint32_t)(mbar)), "r"((uint32_t)(cnt)) : "memory")
#define MBAR_EXPECT_TX(mbar, tx) \
    asm volatile("mbarrier.arrive.expect_tx.shared.b64 _, [%0], %1;" :: "r"((uint32_t)(mbar)), "r"((uint32_t)(tx)) : "memory")
#define MBAR_WAIT(mbar, parity) do {                                          \
    uint32_t _m = (uint32_t)(mbar); uint32_t _p = (uint32_t)(parity);         \
    asm volatile(                                                             \
        "{\n\t.reg .pred P1;\n\t"                                             \
        "WAIT_LOOP_%=:\n\t"                                                   \
        "mbarrier.try_wait.parity.acquire.cta.shared::cta.b64 P1, [%0], %1, 0x989680;\n\t" \
        "@P1 bra.uni WAIT_DONE_%=;\n\t"                                       \
        "bra.uni WAIT_LOOP_%=;\n\t"                                           \
        "WAIT_DONE_%=:\n\t}"                                                  \
        :: "r"(_m), "r"(_p) : "memory");                                      \
} while (0)
#define BULK_G2S(dst, src, bytes, mbar) \
    asm volatile("cp.async.bulk.shared::cta.global.mbarrier::complete_tx::bytes [%0], [%1], %2, [%3];" \
                 :: "r"((uint32_t)(dst)), "l"(src), "r"((uint32_t)(bytes)), "r"((uint32_t)(mbar)) : "memory")

// ---------------- prep kernels ----------------
__global__ void transpose_kernel(const float* __restrict__ W) {
    int o = blockIdx.x * 256 + threadIdx.x;  // o = k*256 + d
    int k = o >> 8, d = o & 255;
    g_Wt[o] = W[d * 256 + k];
}

// 8 chunks of [256 n][32 k], 64B rows, SW64
__global__ void wprep_kernel(const float* __restrict__ W) {
    int idx = blockIdx.x * 256 + threadIdx.x;  // d*256 + k
    int d = idx >> 8, k = idx & 255;
    float w = W[idx];
    __nv_bfloat16 h = __float2bfloat16_rn(w);
    float r = w - __bfloat162float(h);
    __nv_bfloat16 l = __float2bfloat16_rn(r);
    int chunk = k >> 5, kc = k & 31;
    int off = d * 64 + kc * 2;
    int sw = off ^ ((off >> 3) & 0x30);      // SW64
    int pos = chunk * 16384 + sw;
    *(unsigned short*)(g_WB_hi + pos) = __bfloat16_as_ushort(h);
    *(unsigned short*)(g_WB_lo + pos) = __bfloat16_as_ushort(l);
}

// ---------------- high-occupancy projections (R12 exact) ----------------
__global__ void __launch_bounds__(256, 6)
proj_nodes_simple(const float* __restrict__ A, const float* __restrict__ bias) {
    __shared__ float As[4][256];
    const int tid = threadIdx.x;
    const int r0 = blockIdx.x * 4;

#pragma unroll
    for (int q = 0; q < 4; q++)
        As[q][tid] = A[(size_t)(r0 + q) * 256 + tid];
    __syncthreads();

    float a0 = 0.0f, a1 = 0.0f, a2 = 0.0f, a3 = 0.0f;
#pragma unroll 8
    for (int k = 0; k < 256; k++) {
        float wv = g_Wt[k * 256 + tid];
        a0 = fmaf(As[0][k], wv, a0);
        a1 = fmaf(As[1][k], wv, a1);
        a2 = fmaf(As[2][k], wv, a2);
        a3 = fmaf(As[3][k], wv, a3);
    }
    float bv = bias[tid];
    g_node_p[(size_t)(r0 + 0) * 256 + tid] = a0 + bv;
    g_node_p[(size_t)(r0 + 1) * 256 + tid] = a1 + bv;
    g_node_p[(size_t)(r0 + 2) * 256 + tid] = a2 + bv;
    g_node_p[(size_t)(r0 + 3) * 256 + tid] = a3 + bv;
}

__global__ void __launch_bounds__(256, 6)
proj_final_simple(const float* __restrict__ bias, float* __restrict__ C) {
    __shared__ float As[4][256];
    const int tid = threadIdx.x;
    const int r0 = blockIdx.x * 4;

#pragma unroll
    for (int q = 0; q < 4; q++)
        As[q][tid] = g_out0[(size_t)(r0 + q) * 256 + tid];
    __syncthreads();

    float a0 = 0.0f, a1 = 0.0f, a2 = 0.0f, a3 = 0.0f;
#pragma unroll 8
    for (int k = 0; k < 256; k++) {
        float wv = g_Wt[k * 256 + tid];
        a0 = fmaf(As[0][k], wv, a0);
        a1 = fmaf(As[1][k], wv, a1);
        a2 = fmaf(As[2][k], wv, a2);
        a3 = fmaf(As[3][k], wv, a3);
    }
    float bv = bias[tid];
    C[(size_t)(r0 + 0) * 256 + tid] = a0 + bv;
    C[(size_t)(r0 + 1) * 256 + tid] = a1 + bv;
    C[(size_t)(r0 + 2) * 256 + tid] = a2 + bv;
    C[(size_t)(r0 + 3) * 256 + tid] = a3 + bv;
}

// ---------------- edge projection + scores (R13 exact: 8 x 32-k chunks, W dbl-buffered) ----------------
// SMEM: A slots: 2 x (4KB hi + 4KB lo)   @ 0      (16KB)
//       W slots: 2 x (16KB hi + 16KB lo) @ 16384  (64KB)
// Total 80KB -> 2 CTAs/SM.
#define SM_A   0
#define SM_W   16384
#define SM_DYN 81920
#define NTHR   256

__device__ __forceinline__ void cvt_store_a(char* sm, int slot, int flat, float4 v) {
    __nv_bfloat16 hx = __float2bfloat16_rn(v.x);
    __nv_bfloat16 hy = __float2bfloat16_rn(v.y);
    __nv_bfloat16 hz = __float2bfloat16_rn(v.z);
    __nv_bfloat16 hw = __float2bfloat16_rn(v.w);
    __nv_bfloat16 lx = __float2bfloat16_rn(v.x - __bfloat162float(hx));
    __nv_bfloat16 ly = __float2bfloat16_rn(v.y - __bfloat162float(hy));
    __nv_bfloat16 lz = __float2bfloat16_rn(v.z - __bfloat162float(hz));
    __nv_bfloat16 lw = __float2bfloat16_rn(v.w - __bfloat162float(hw));
    uint2 hi2, lo2;
    hi2.x = (uint32_t)__bfloat16_as_ushort(hx) | ((uint32_t)__bfloat16_as_ushort(hy) << 16);
    hi2.y = (uint32_t)__bfloat16_as_ushort(hz) | ((uint32_t)__bfloat16_as_ushort(hw) << 16);
    lo2.x = (uint32_t)__bfloat16_as_ushort(lx) | ((uint32_t)__bfloat16_as_ushort(ly) << 16);
    lo2.y = (uint32_t)__bfloat16_as_ushort(lz) | ((uint32_t)__bfloat16_as_ushort(lw) << 16);
    int row = flat >> 3, c4 = flat & 7;      // 8 float4 per 32-k row
    int off = row * 64 + c4 * 8;
    int sw = off ^ ((off >> 3) & 0x30);      // SW64
    char* base = sm + SM_A + slot * 8192;
    *(uint2*)(base + sw) = hi2;
    *(uint2*)(base + 4096 + sw) = lo2;
}

__global__ void __launch_bounds__(NTHR, 2)
edge_score_mma(const float* __restrict__ edges, const float* __restrict__ bias,
               float* __restrict__ scores) {
    extern __shared__ char sm[];
    __shared__ __align__(8) unsigned long long mbarr[2];
    const uint32_t smb = smem_u32(sm);
    const uint32_t mb0 = smem_u32(&mbarr[0]);
    const int tid = threadIdx.x, wid = tid >> 5, lane = tid & 31;
    const int jt = blockIdx.x, i = blockIdx.y, b = blockIdx.z;
    const int wm = (wid >> 2) * 32;
    const int wn = (wid & 3) * 64;

    const float* A = edges + ((((size_t)b * N_SZ + i) * N_SZ) + (size_t)jt * 64) * D_MODEL;
    const unsigned long long gwh = (unsigned long long)__cvta_generic_to_global(g_WB_hi);
    const unsigned long long gwl = (unsigned long long)__cvta_generic_to_global(g_WB_lo);

    if (tid == 0) { MBAR_INIT(mb0, 1); MBAR_INIT(mb0 + 8, 1); }
    __syncthreads();

    if (tid == 0) {
        MBAR_EXPECT_TX(mb0, 32768);
        BULK_G2S(smb + SM_W, gwh, 16384, mb0);
        BULK_G2S(smb + SM_W + 16384, gwl, 16384, mb0);
    }
#pragma unroll
    for (int q = 0; q < 2; q++) {
        int flat = q * NTHR + tid;
        float4 v = *(const float4*)(A + (size_t)(flat >> 3) * 256 + (flat & 7) * 4);
        cvt_store_a(sm, 0, flat, v);
    }
    __syncthreads();

    float acc[2][8][4];
#pragma unroll
    for (int mf = 0; mf < 2; mf++)
#pragma unroll
        for (int nf = 0; nf < 8; nf++)
#pragma unroll
            for (int c = 0; c < 4; c++) acc[mf][nf][c] = 0.0f;

    uint32_t apre[2], axor[2];
#pragma unroll
    for (int mf = 0; mf < 2; mf++) {
        int row = wm + mf * 16 + (lane & 15);
        apre[mf] = row * 64;
        axor[mf] = (row & 6) << 3;           // SW64
    }
    const int koffA = (lane >> 4) * 8;
    uint32_t bpre[4], bxor[4];
#pragma unroll
    for (int gb = 0; gb < 4; gb++) {
        int n = wn + gb * 16 + (((lane >> 3) >= 2) ? 8 : 0) + (lane & 7);
        bpre[gb] = n * 64;
        bxor[gb] = (n & 6) << 3;             // SW64
    }
    const int kcB = ((lane >> 3) & 1) * 8;

#pragma unroll 1
    for (int ch = 0; ch < 8; ch++) {
        const int cur = ch & 1, nxt = cur ^ 1;
        if (ch < 7 && tid == 0) {
            MBAR_EXPECT_TX(mb0 + 8 * nxt, 32768);
            BULK_G2S(smb + SM_W + nxt * 32768, gwh + (ch + 1) * 16384, 16384, mb0 + 8 * nxt);
            BULK_G2S(smb + SM_W + nxt * 32768 + 16384, gwl + (ch + 1) * 16384, 16384, mb0 + 8 * nxt);
        }
        MBAR_WAIT(mb0 + 8 * cur, (ch >> 1) & 1);

        const uint32_t abase = smb + SM_A + cur * 8192;
        const uint32_t wbase = smb + SM_W + cur * 32768;

#pragma unroll
        for (int ks = 0; ks < 2; ks++) {
            float4 v0;
            int f0 = ks * NTHR + tid;
            if (ch < 7)
                v0 = *(const float4*)(A + (ch + 1) * 32 + (size_t)(f0 >> 3) * 256 + (f0 & 7) * 4);

            const uint32_t kg2 = (uint32_t)((ks * 16 + koffA) * 2);
            uint32_t ah[2][4], al[2][4];
#pragma unroll
            for (int mf = 0; mf < 2; mf++) {
                uint32_t ad = abase + apre[mf] + (kg2 ^ axor[mf]);
                ldsm_x4(ah[mf], ad);
                ldsm_x4(al[mf], ad + 4096);
            }
            const uint32_t kc2 = (uint32_t)((ks * 16 + kcB) * 2);
#pragma unroll
            for (int gb = 0; gb < 4; gb++) {
                uint32_t bh[4], bl[4];
                uint32_t bd = wbase + bpre[gb] + (kc2 ^ bxor[gb]);
                ldsm_x4(bh, bd);
                ldsm_x4(bl, bd + 16384);
#pragma unroll
                for (int mf = 0; mf < 2; mf++)
#pragma unroll
                    for (int s2 = 0; s2 < 2; s2++)
                        mma_bf16(acc[mf][gb * 2 + s2], ah[mf], &bh[s2 * 2]);
#pragma unroll
                for (int mf = 0; mf < 2; mf++)
#pragma unroll
                    for (int s2 = 0; s2 < 2; s2++)
                        mma_bf16(acc[mf][gb * 2 + s2], ah[mf], &bl[s2 * 2]);
#pragma unroll
                for (int mf = 0; mf < 2; mf++)
#pragma unroll
                    for (int s2 = 0; s2 < 2; s2++)
                        mma_bf16(acc[mf][gb * 2 + s2], al[mf], &bh[s2 * 2]);
            }

            if (ch < 7) cvt_store_a(sm, nxt, f0, v0);
        }
        __syncthreads();
    }

    // ---- epilogue (R13 exact) ----
    {
        float* nps = (float*)sm;
        const float* src = g_node_p + ((size_t)b * N_SZ + jt * 64) * 256;
        int row = tid >> 2, q4 = tid & 3;
        const float4* s4 = (const float4*)(src + (size_t)row * 256) + q4 * 16;
        float4* d4 = (float4*)(nps + row * 260) + q4 * 16;
#pragma unroll
        for (int q = 0; q < 16; q++) d4[q] = s4[q];
    }
    __syncthreads();

    float pb[16], p1[16];
    {
        const float* npi = g_node_p + ((size_t)b * N_SZ + i) * 256;
#pragma unroll
        for (int h = 0; h < 2; h++)
#pragma unroll
            for (int nf = 0; nf < 4; nf++)
#pragma unroll
                for (int v2 = 0; v2 < 2; v2++) {
                    int idx = h * 8 + nf * 2 + v2;
                    int d = wn + (h * 4 + nf) * 8 + (lane & 3) * 2 + v2;
                    float bv = bias[d];
                    pb[idx] = bv;
                    p1[idx] = bv + npi[d];
                }
    }

    const float* nps = (const float*)sm;
#pragma unroll
    for (int mf = 0; mf < 2; mf++) {
#pragma unroll
        for (int half = 0; half < 2; half++) {
            int r = wm + mf * 16 + (lane >> 2) + half * 8;
            const float* nj = nps + r * 260 + wn;
#pragma unroll
            for (int h = 0; h < 2; h++) {
                float s = 0.0f;
#pragma unroll
                for (int nf = 0; nf < 4; nf++)
#pragma unroll
                    for (int v2 = 0; v2 < 2; v2++) {
                        int idx = h * 8 + nf * 2 + v2;
                        float a = acc[mf][h * 4 + nf][half * 2 + v2];
                        float njv = nj[(h * 4 + nf) * 8 + (lane & 3) * 2 + v2];
                        s += (a + p1[idx]) * (a + pb[idx] + njv);
                    }
                s += __shfl_xor_sync(0xffffffffu, s, 1);
                s += __shfl_xor_sync(0xffffffffu, s, 2);
                if ((lane & 3) == 0) {
                    int hg = (wn >> 5) + h;
                    scores[((((size_t)b * NHEAD + hg) * N_SZ + i) << 8) + jt * 64 + r] =
                        10.0f * tanhf(s * 0.17677669529663687f);
                }
            }
        }
    }
}

// ---------------- softmax + AV v2: V staged in smem, 32 i-rows per CTA ----------------
#define SAV_SMEM 65536
__global__ void __launch_bounds__(256, 2)
softmax_av2(float* __restrict__ attn) {
    extern __shared__ char savsm[];
    float* V = (float*)savsm;            // [256 j][32 d]
    float* P = V + 256 * 32;             // [32 r][256 j]

    const int i0 = blockIdx.x * 32, h = blockIdx.y, b = blockIdx.z;
    const int tid = threadIdx.x, wid = tid >> 5, lane = tid & 31;

    // stage V head slice: V[j][d] = node_p[b, j, h*32+d]
    {
        const float* npb = g_node_p + (size_t)b * N_SZ * D_MODEL + h * 32;
#pragma unroll
        for (int q = 0; q < 8; q++) {
            int flat = q * 256 + tid;        // 2048 float4-slots: j = flat>>3, f4 = flat&7
            int j = flat >> 3, f4 = flat & 7;
            *(float4*)&V[j * 32 + f4 * 4] = *(const float4*)(npb + (size_t)j * 256 + f4 * 4);
        }
    }

    // softmax: warp wid handles rows wid, wid+8, wid+16, wid+24
#pragma unroll
    for (int q = 0; q < 4; q++) {
        int r = wid + q * 8;
        float* srow = attn + ((((size_t)(b * NHEAD + h) * N_SZ) + i0 + r) << 8);
        float4 x0 = *(const float4*)(srow + lane * 8);
        float4 x1 = *(const float4*)(srow + lane * 8 + 4);
        float m = fmaxf(fmaxf(fmaxf(x0.x, x0.y), fmaxf(x0.z, x0.w)),
                        fmaxf(fmaxf(x1.x, x1.y), fmaxf(x1.z, x1.w)));
#pragma unroll
        for (int off = 16; off > 0; off >>= 1)
            m = fmaxf(m, __shfl_xor_sync(0xffffffffu, m, off));
        float e0 = __expf(x0.x - m), e1 = __expf(x0.y - m), e2 = __expf(x0.z - m), e3 = __expf(x0.w - m);
        float e4 = __expf(x1.x - m), e5 = __expf(x1.y - m), e6 = __expf(x1.z - m), e7 = __expf(x1.w - m);
        float t = e0 + e1 + e2 + e3 + e4 + e5 + e6 + e7;
#pragma unroll
        for (int off = 16; off > 0; off >>= 1)
            t += __shfl_xor_sync(0xffffffffu, t, off);
        float inv = 1.0f / t;
        float4 p0 = make_float4(e0 * inv, e1 * inv, e2 * inv, e3 * inv);
        float4 p1 = make_float4(e4 * inv, e5 * inv, e6 * inv, e7 * inv);
        *(float4*)&P[r * 256 + lane * 8] = p0;
        *(float4*)&P[r * 256 + lane * 8 + 4] = p1;
        *(float4*)(srow + lane * 8) = p0;
        *(float4*)(srow + lane * 8 + 4) = p1;
    }
    __syncthreads();

    // AV: out0[b, i0+r, h*32+d] = sum_j P[r][j] * V[j][d];  d = lane, rows wid+8q
    const int d = lane;
    float a0 = 0.0f, a1 = 0.0f, a2 = 0.0f, a3 = 0.0f;
    const float* Prow0 = &P[wid * 256];
#pragma unroll 4
    for (int j = 0; j < 256; j++) {
        float vv = V[j * 32 + d];
        a0 = fmaf(Prow0[j], vv, a0);
        a1 = fmaf(Prow0[j + 8 * 256], vv, a1);
        a2 = fmaf(Prow0[j + 16 * 256], vv, a2);
        a3 = fmaf(Prow0[j + 24 * 256], vv, a3);
    }
    float* ob = g_out0 + ((size_t)(b * N_SZ + i0)) * D_MODEL + h * 32 + d;
    ob[(size_t)(wid + 0) * 256] = a0;
    ob[(size_t)(wid + 8) * 256] = a1;
    ob[(size_t)(wid + 16) * 256] = a2;
    ob[(size_t)(wid + 24) * 256] = a3;
}

// ---------------- launch ----------------
extern "C" void kernel_launch(void* const* d_in, const int* in_sizes, int n_in,
                              void* d_out, int out_size) {
    const float* nodes = (const float*)d_in[0];
    const float* edges = (const float*)d_in[1];
    const float* W     = (const float*)d_in[2];
    const float* bias  = (const float*)d_in[3];

    float* out  = (float*)d_out;
    float* attn = out + B_SZ * N_SZ * D_MODEL;

    cudaFuncSetAttribute(edge_score_mma, cudaFuncAttributeMaxDynamicSharedMemorySize, SM_DYN);
    cudaFuncSetAttribute(softmax_av2, cudaFuncAttributeMaxDynamicSharedMemorySize, SAV_SMEM);

    transpose_kernel<<<256, 256>>>(W);                          // 0
    wprep_kernel<<<256, 256>>>(W);                              // 1
    proj_nodes_simple<<<256, 256>>>(nodes, bias);               // 2
    dim3 g2(4, N_SZ, B_SZ);
    edge_score_mma<<<g2, NTHR, SM_DYN>>>(edges, bias, attn);    // 3 (profiled)
    dim3 g3(N_SZ / 32, NHEAD, B_SZ);
    softmax_av2<<<g3, 256, SAV_SMEM>>>(attn);                   // 4
    proj_final_simple<<<256, 256>>>(bias, out);                 // 5
}

// round 16
// speedup vs baseline: 1.0688x; 1.0005x over previous
#include <cuda_runtime.h>
#include <cuda_bf16.h>
#include <math.h>
#include <stdint.h>

#define D_MODEL 256
#define NHEAD   8
#define HEAD_DIM 32
#define B_SZ    4
#define N_SZ    256

// ---------------- device scratch ----------------
__device__ float g_Wt[D_MODEL * D_MODEL];
__device__ float g_node_p[B_SZ * N_SZ * D_MODEL];
__device__ float g_out0[B_SZ * N_SZ * D_MODEL];
// W bf16 splits, 8 K-chunks of [256 n][32 k] bf16, 64B rows, SW64 swizzle (16KB/chunk)
__device__ __align__(128) unsigned char g_WB_hi[131072];
__device__ __align__(128) unsigned char g_WB_lo[131072];

__device__ __forceinline__ uint32_t smem_u32(const void* p) {
    uint32_t a;
    asm("{ .reg .u64 t; cvta.to.shared.u64 t, %1; cvt.u32.u64 %0, t; }" : "=r"(a) : "l"(p));
    return a;
}

__device__ __forceinline__ void ldsm_x4(uint32_t r[4], uint32_t addr) {
    asm volatile("ldmatrix.sync.aligned.m8n8.x4.shared.b16 {%0,%1,%2,%3}, [%4];"
                 : "=r"(r[0]), "=r"(r[1]), "=r"(r[2]), "=r"(r[3]) : "r"(addr));
}

__device__ __forceinline__ void mma_bf16(float c[4], const uint32_t a[4], const uint32_t b[2]) {
    asm volatile(
        "mma.sync.aligned.m16n8k16.row.col.f32.bf16.bf16.f32 "
        "{%0,%1,%2,%3}, {%4,%5,%6,%7}, {%8,%9}, {%0,%1,%2,%3};"
        : "+f"(c[0]), "+f"(c[1]), "+f"(c[2]), "+f"(c[3])
        : "r"(a[0]), "r"(a[1]), "r"(a[2]), "r"(a[3]), "r"(b[0]), "r"(b[1]));
}

#define MBAR_INIT(mbar, cnt) \
    asm volatile("mbarrier.init.shared.b64 [%0], %1;" :: "r"((uint32_t)(mbar)), "r"((uint32_t)(cnt)) : "memory")
#define MBAR_EXPECT_TX(mbar, tx) \
    asm volatile("mbarrier.arrive.expect_tx.shared.b64 _, [%0], %1;" :: "r"((uint32_t)(mbar)), "r"((uint32_t)(tx)) : "memory")
#define MBAR_WAIT(mbar, parity) do {                                          \
    uint32_t _m = (uint32_t)(mbar); uint32_t _p = (uint32_t)(parity);         \
    asm volatile(                                                             \
        "{\n\t.reg .pred P1;\n\t"                                             \
        "WAIT_LOOP_%=:\n\t"                                                   \
        "mbarrier.try_wait.parity.acquire.cta.shared::cta.b64 P1, [%0], %1, 0x989680;\n\t" \
        "@P1 bra.uni WAIT_DONE_%=;\n\t"                                       \
        "bra.uni WAIT_LOOP_%=;\n\t"                                           \
        "WAIT_DONE_%=:\n\t}"                                                  \
        :: "r"(_m), "r"(_p) : "memory");                                      \
} while (0)
#define BULK_G2S(dst, src, bytes, mbar) \
    asm volatile("cp.async.bulk.shared::cta.global.mbarrier::complete_tx::bytes [%0], [%1], %2, [%3];" \
                 :: "r"((uint32_t)(dst)), "l"(src), "r"((uint32_t)(bytes)), "r"((uint32_t)(mbar)) : "memory")

// ---------------- prep kernels ----------------
__global__ void transpose_kernel(const float* __restrict__ W) {
    int o = blockIdx.x * 256 + threadIdx.x;  // o = k*256 + d
    int k = o >> 8, d = o & 255;
    g_Wt[o] = W[d * 256 + k];
}

// 8 chunks of [256 n][32 k], 64B rows, SW64
__global__ void wprep_kernel(const float* __restrict__ W) {
    int idx = blockIdx.x * 256 + threadIdx.x;  // d*256 + k
    int d = idx >> 8, k = idx & 255;
    float w = W[idx];
    __nv_bfloat16 h = __float2bfloat16_rn(w);
    float r = w - __bfloat162float(h);
    __nv_bfloat16 l = __float2bfloat16_rn(r);
    int chunk = k >> 5, kc = k & 31;
    int off = d * 64 + kc * 2;
    int sw = off ^ ((off >> 3) & 0x30);      // SW64
    int pos = chunk * 16384 + sw;
    *(unsigned short*)(g_WB_hi + pos) = __bfloat16_as_ushort(h);
    *(unsigned short*)(g_WB_lo + pos) = __bfloat16_as_ushort(l);
}

// ---------------- high-occupancy projections (R12 exact) ----------------
__global__ void __launch_bounds__(256, 6)
proj_nodes_simple(const float* __restrict__ A, const float* __restrict__ bias) {
    __shared__ float As[4][256];
    const int tid = threadIdx.x;
    const int r0 = blockIdx.x * 4;

#pragma unroll
    for (int q = 0; q < 4; q++)
        As[q][tid] = A[(size_t)(r0 + q) * 256 + tid];
    __syncthreads();

    float a0 = 0.0f, a1 = 0.0f, a2 = 0.0f, a3 = 0.0f;
#pragma unroll 8
    for (int k = 0; k < 256; k++) {
        float wv = g_Wt[k * 256 + tid];
        a0 = fmaf(As[0][k], wv, a0);
        a1 = fmaf(As[1][k], wv, a1);
        a2 = fmaf(As[2][k], wv, a2);
        a3 = fmaf(As[3][k], wv, a3);
    }
    float bv = bias[tid];
    g_node_p[(size_t)(r0 + 0) * 256 + tid] = a0 + bv;
    g_node_p[(size_t)(r0 + 1) * 256 + tid] = a1 + bv;
    g_node_p[(size_t)(r0 + 2) * 256 + tid] = a2 + bv;
    g_node_p[(size_t)(r0 + 3) * 256 + tid] = a3 + bv;
}

__global__ void __launch_bounds__(256, 6)
proj_final_simple(const float* __restrict__ bias, float* __restrict__ C) {
    __shared__ float As[4][256];
    const int tid = threadIdx.x;
    const int r0 = blockIdx.x * 4;

#pragma unroll
    for (int q = 0; q < 4; q++)
        As[q][tid] = g_out0[(size_t)(r0 + q) * 256 + tid];
    __syncthreads();

    float a0 = 0.0f, a1 = 0.0f, a2 = 0.0f, a3 = 0.0f;
#pragma unroll 8
    for (int k = 0; k < 256; k++) {
        float wv = g_Wt[k * 256 + tid];
        a0 = fmaf(As[0][k], wv, a0);
        a1 = fmaf(As[1][k], wv, a1);
        a2 = fmaf(As[2][k], wv, a2);
        a3 = fmaf(As[3][k], wv, a3);
    }
    float bv = bias[tid];
    C[(size_t)(r0 + 0) * 256 + tid] = a0 + bv;
    C[(size_t)(r0 + 1) * 256 + tid] = a1 + bv;
    C[(size_t)(r0 + 2) * 256 + tid] = a2 + bv;
    C[(size_t)(r0 + 3) * 256 + tid] = a3 + bv;
}

// ---------------- edge projection + scores: pass-major MMA schedule ----------------
// SMEM: A slots: 2 x (4KB hi + 4KB lo)   @ 0      (16KB)
//       W slots: 2 x (16KB hi + 16KB lo) @ 16384  (64KB)
// Total 80KB -> 2 CTAs/SM.
#define SM_A   0
#define SM_W   16384
#define SM_DYN 81920
#define NTHR   256

__device__ __forceinline__ void cvt_store_a(char* sm, int slot, int flat, float4 v) {
    __nv_bfloat16 hx = __float2bfloat16_rn(v.x);
    __nv_bfloat16 hy = __float2bfloat16_rn(v.y);
    __nv_bfloat16 hz = __float2bfloat16_rn(v.z);
    __nv_bfloat16 hw = __float2bfloat16_rn(v.w);
    __nv_bfloat16 lx = __float2bfloat16_rn(v.x - __bfloat162float(hx));
    __nv_bfloat16 ly = __float2bfloat16_rn(v.y - __bfloat162float(hy));
    __nv_bfloat16 lz = __float2bfloat16_rn(v.z - __bfloat162float(hz));
    __nv_bfloat16 lw = __float2bfloat16_rn(v.w - __bfloat162float(hw));
    uint2 hi2, lo2;
    hi2.x = (uint32_t)__bfloat16_as_ushort(hx) | ((uint32_t)__bfloat16_as_ushort(hy) << 16);
    hi2.y = (uint32_t)__bfloat16_as_ushort(hz) | ((uint32_t)__bfloat16_as_ushort(hw) << 16);
    lo2.x = (uint32_t)__bfloat16_as_ushort(lx) | ((uint32_t)__bfloat16_as_ushort(ly) << 16);
    lo2.y = (uint32_t)__bfloat16_as_ushort(lz) | ((uint32_t)__bfloat16_as_ushort(lw) << 16);
    int row = flat >> 3, c4 = flat & 7;      // 8 float4 per 32-k row
    int off = row * 64 + c4 * 8;
    int sw = off ^ ((off >> 3) & 0x30);      // SW64
    char* base = sm + SM_A + slot * 8192;
    *(uint2*)(base + sw) = hi2;
    *(uint2*)(base + 4096 + sw) = lo2;
}

__global__ void __launch_bounds__(NTHR, 2)
edge_score_mma(const float* __restrict__ edges, const float* __restrict__ bias,
               float* __restrict__ scores) {
    extern __shared__ char sm[];
    __shared__ __align__(8) unsigned long long mbarr[2];
    const uint32_t smb = smem_u32(sm);
    const uint32_t mb0 = smem_u32(&mbarr[0]);
    const int tid = threadIdx.x, wid = tid >> 5, lane = tid & 31;
    const int jt = blockIdx.x, i = blockIdx.y, b = blockIdx.z;
    const int wm = (wid >> 2) * 32;
    const int wn = (wid & 3) * 64;

    const float* A = edges + ((((size_t)b * N_SZ + i) * N_SZ) + (size_t)jt * 64) * D_MODEL;
    const unsigned long long gwh = (unsigned long long)__cvta_generic_to_global(g_WB_hi);
    const unsigned long long gwl = (unsigned long long)__cvta_generic_to_global(g_WB_lo);

    if (tid == 0) { MBAR_INIT(mb0, 1); MBAR_INIT(mb0 + 8, 1); }
    __syncthreads();

    if (tid == 0) {
        MBAR_EXPECT_TX(mb0, 32768);
        BULK_G2S(smb + SM_W, gwh, 16384, mb0);
        BULK_G2S(smb + SM_W + 16384, gwl, 16384, mb0);
    }
#pragma unroll
    for (int q = 0; q < 2; q++) {
        int flat = q * NTHR + tid;
        float4 v = *(const float4*)(A + (size_t)(flat >> 3) * 256 + (flat & 7) * 4);
        cvt_store_a(sm, 0, flat, v);
    }
    __syncthreads();

    float acc[2][8][4];
#pragma unroll
    for (int mf = 0; mf < 2; mf++)
#pragma unroll
        for (int nf = 0; nf < 8; nf++)
#pragma unroll
            for (int c = 0; c < 4; c++) acc[mf][nf][c] = 0.0f;

    uint32_t apre[2], axor[2];
#pragma unroll
    for (int mf = 0; mf < 2; mf++) {
        int row = wm + mf * 16 + (lane & 15);
        apre[mf] = row * 64;
        axor[mf] = (row & 6) << 3;           // SW64
    }
    const int koffA = (lane >> 4) * 8;
    uint32_t bpre[4], bxor[4];
#pragma unroll
    for (int gb = 0; gb < 4; gb++) {
        int n = wn + gb * 16 + (((lane >> 3) >= 2) ? 8 : 0) + (lane & 7);
        bpre[gb] = n * 64;
        bxor[gb] = (n & 6) << 3;             // SW64
    }
    const int kcB = ((lane >> 3) & 1) * 8;

#pragma unroll 1
    for (int ch = 0; ch < 8; ch++) {
        const int cur = ch & 1, nxt = cur ^ 1;
        if (ch < 7 && tid == 0) {
            MBAR_EXPECT_TX(mb0 + 8 * nxt, 32768);
            BULK_G2S(smb + SM_W + nxt * 32768, gwh + (ch + 1) * 16384, 16384, mb0 + 8 * nxt);
            BULK_G2S(smb + SM_W + nxt * 32768 + 16384, gwl + (ch + 1) * 16384, 16384, mb0 + 8 * nxt);
        }
        MBAR_WAIT(mb0 + 8 * cur, (ch >> 1) & 1);

        const uint32_t abase = smb + SM_A + cur * 8192;
        const uint32_t wbase = smb + SM_W + cur * 32768;

#pragma unroll
        for (int ks = 0; ks < 2; ks++) {
            float4 v0;
            int f0 = ks * NTHR + tid;
            if (ch < 7)
                v0 = *(const float4*)(A + (ch + 1) * 32 + (size_t)(f0 >> 3) * 256 + (f0 & 7) * 4);

            const uint32_t kg2 = (uint32_t)((ks * 16 + koffA) * 2);
            const uint32_t kc2 = (uint32_t)((ks * 16 + kcB) * 2);

            // preload ALL B-hi fragments (kept live across passes 1 and 3)
            uint32_t bh[4][4];
#pragma unroll
            for (int gb = 0; gb < 4; gb++)
                ldsm_x4(bh[gb], wbase + bpre[gb] + (kc2 ^ bxor[gb]));
            // A fragments
            uint32_t ah[2][4], al[2][4];
#pragma unroll
            for (int mf = 0; mf < 2; mf++) {
                uint32_t ad = abase + apre[mf] + (kg2 ^ axor[mf]);
                ldsm_x4(ah[mf], ad);
                ldsm_x4(al[mf], ad + 4096);
            }

            // pass 1: ah x bh — 16 independent acc chains
#pragma unroll
            for (int gb = 0; gb < 4; gb++)
#pragma unroll
                for (int mf = 0; mf < 2; mf++)
#pragma unroll
                    for (int s2 = 0; s2 < 2; s2++)
                        mma_bf16(acc[mf][gb * 2 + s2], ah[mf], &bh[gb][s2 * 2]);

            // pass 2: ah x bl — stream bl one gb at a time (4 regs live)
#pragma unroll
            for (int gb = 0; gb < 4; gb++) {
                uint32_t bl[4];
                ldsm_x4(bl, wbase + 16384 + bpre[gb] + (kc2 ^ bxor[gb]));
#pragma unroll
                for (int mf = 0; mf < 2; mf++)
#pragma unroll
                    for (int s2 = 0; s2 < 2; s2++)
                        mma_bf16(acc[mf][gb * 2 + s2], ah[mf], &bl[s2 * 2]);
            }

            // pass 3: al x bh — 16 independent acc chains, reuses held bh
#pragma unroll
            for (int gb = 0; gb < 4; gb++)
#pragma unroll
                for (int mf = 0; mf < 2; mf++)
#pragma unroll
                    for (int s2 = 0; s2 < 2; s2++)
                        mma_bf16(acc[mf][gb * 2 + s2], al[mf], &bh[gb][s2 * 2]);

            if (ch < 7) cvt_store_a(sm, nxt, f0, v0);
        }
        __syncthreads();
    }

    // ---- epilogue (R13 exact) ----
    {
        float* nps = (float*)sm;
        const float* src = g_node_p + ((size_t)b * N_SZ + jt * 64) * 256;
        int row = tid >> 2, q4 = tid & 3;
        const float4* s4 = (const float4*)(src + (size_t)row * 256) + q4 * 16;
        float4* d4 = (float4*)(nps + row * 260) + q4 * 16;
#pragma unroll
        for (int q = 0; q < 16; q++) d4[q] = s4[q];
    }
    __syncthreads();

    float pb[16], p1[16];
    {
        const float* npi = g_node_p + ((size_t)b * N_SZ + i) * 256;
#pragma unroll
        for (int h = 0; h < 2; h++)
#pragma unroll
            for (int nf = 0; nf < 4; nf++)
#pragma unroll
                for (int v2 = 0; v2 < 2; v2++) {
                    int idx = h * 8 + nf * 2 + v2;
                    int d = wn + (h * 4 + nf) * 8 + (lane & 3) * 2 + v2;
                    float bv = bias[d];
                    pb[idx] = bv;
                    p1[idx] = bv + npi[d];
                }
    }

    const float* nps = (const float*)sm;
#pragma unroll
    for (int mf = 0; mf < 2; mf++) {
#pragma unroll
        for (int half = 0; half < 2; half++) {
            int r = wm + mf * 16 + (lane >> 2) + half * 8;
            const float* nj = nps + r * 260 + wn;
#pragma unroll
            for (int h = 0; h < 2; h++) {
                float s = 0.0f;
#pragma unroll
                for (int nf = 0; nf < 4; nf++)
#pragma unroll
                    for (int v2 = 0; v2 < 2; v2++) {
                        int idx = h * 8 + nf * 2 + v2;
                        float a = acc[mf][h * 4 + nf][half * 2 + v2];
                        float njv = nj[(h * 4 + nf) * 8 + (lane & 3) * 2 + v2];
                        s += (a + p1[idx]) * (a + pb[idx] + njv);
                    }
                s += __shfl_xor_sync(0xffffffffu, s, 1);
                s += __shfl_xor_sync(0xffffffffu, s, 2);
                if ((lane & 3) == 0) {
                    int hg = (wn >> 5) + h;
                    scores[((((size_t)b * NHEAD + hg) * N_SZ + i) << 8) + jt * 64 + r] =
                        10.0f * tanhf(s * 0.17677669529663687f);
                }
            }
        }
    }
}

// ---------------- softmax + AV v2 (R15 exact) ----------------
#define SAV_SMEM 65536
__global__ void __launch_bounds__(256, 2)
softmax_av2(float* __restrict__ attn) {
    extern __shared__ char savsm[];
    float* V = (float*)savsm;            // [256 j][32 d]
    float* P = V + 256 * 32;             // [32 r][256 j]

    const int i0 = blockIdx.x * 32, h = blockIdx.y, b = blockIdx.z;
    const int tid = threadIdx.x, wid = tid >> 5, lane = tid & 31;

    {
        const float* npb = g_node_p + (size_t)b * N_SZ * D_MODEL + h * 32;
#pragma unroll
        for (int q = 0; q < 8; q++) {
            int flat = q * 256 + tid;
            int j = flat >> 3, f4 = flat & 7;
            *(float4*)&V[j * 32 + f4 * 4] = *(const float4*)(npb + (size_t)j * 256 + f4 * 4);
        }
    }

#pragma unroll
    for (int q = 0; q < 4; q++) {
        int r = wid + q * 8;
        float* srow = attn + ((((size_t)(b * NHEAD + h) * N_SZ) + i0 + r) << 8);
        float4 x0 = *(const float4*)(srow + lane * 8);
        float4 x1 = *(const float4*)(srow + lane * 8 + 4);
        float m = fmaxf(fmaxf(fmaxf(x0.x, x0.y), fmaxf(x0.z, x0.w)),
                        fmaxf(fmaxf(x1.x, x1.y), fmaxf(x1.z, x1.w)));
#pragma unroll
        for (int off = 16; off > 0; off >>= 1)
            m = fmaxf(m, __shfl_xor_sync(0xffffffffu, m, off));
        float e0 = __expf(x0.x - m), e1 = __expf(x0.y - m), e2 = __expf(x0.z - m), e3 = __expf(x0.w - m);
        float e4 = __expf(x1.x - m), e5 = __expf(x1.y - m), e6 = __expf(x1.z - m), e7 = __expf(x1.w - m);
        float t = e0 + e1 + e2 + e3 + e4 + e5 + e6 + e7;
#pragma unroll
        for (int off = 16; off > 0; off >>= 1)
            t += __shfl_xor_sync(0xffffffffu, t, off);
        float inv = 1.0f / t;
        float4 p0 = make_float4(e0 * inv, e1 * inv, e2 * inv, e3 * inv);
        float4 p1 = make_float4(e4 * inv, e5 * inv, e6 * inv, e7 * inv);
        *(float4*)&P[r * 256 + lane * 8] = p0;
        *(float4*)&P[r * 256 + lane * 8 + 4] = p1;
        *(float4*)(srow + lane * 8) = p0;
        *(float4*)(srow + lane * 8 + 4) = p1;
    }
    __syncthreads();

    const int d = lane;
    float a0 = 0.0f, a1 = 0.0f, a2 = 0.0f, a3 = 0.0f;
    const float* Prow0 = &P[wid * 256];
#pragma unroll 4
    for (int j = 0; j < 256; j++) {
        float vv = V[j * 32 + d];
        a0 = fmaf(Prow0[j], vv, a0);
        a1 = fmaf(Prow0[j + 8 * 256], vv, a1);
        a2 = fmaf(Prow0[j + 16 * 256], vv, a2);
        a3 = fmaf(Prow0[j + 24 * 256], vv, a3);
    }
    float* ob = g_out0 + ((size_t)(b * N_SZ + i0)) * D_MODEL + h * 32 + d;
    ob[(size_t)(wid + 0) * 256] = a0;
    ob[(size_t)(wid + 8) * 256] = a1;
    ob[(size_t)(wid + 16) * 256] = a2;
    ob[(size_t)(wid + 24) * 256] = a3;
}

// ---------------- launch ----------------
extern "C" void kernel_launch(void* const* d_in, const int* in_sizes, int n_in,
                              void* d_out, int out_size) {
    const float* nodes = (const float*)d_in[0];
    const float* edges = (const float*)d_in[1];
    const float* W     = (const float*)d_in[2];
    const float* bias  = (const float*)d_in[3];

    float* out  = (float*)d_out;
    float* attn = out + B_SZ * N_SZ * D_MODEL;

    cudaFuncSetAttribute(edge_score_mma, cudaFuncAttributeMaxDynamicSharedMemorySize, SM_DYN);
    cudaFuncSetAttribute(softmax_av2, cudaFuncAttributeMaxDynamicSharedMemorySize, SAV_SMEM);

    transpose_kernel<<<256, 256>>>(W);                          // 0
    wprep_kernel<<<256, 256>>>(W);                              // 1
    proj_nodes_simple<<<256, 256>>>(nodes, bias);               // 2
    dim3 g2(4, N_SZ, B_SZ);
    edge_score_mma<<<g2, NTHR, SM_DYN>>>(edges, bias, attn);    // 3 (profiled)
    dim3 g3(N_SZ / 32, NHEAD, B_SZ);
    softmax_av2<<<g3, 256, SAV_SMEM>>>(attn);                   // 4
    proj_final_simple<<<256, 256>>>(bias, out);                 // 5
}

// round 17
// speedup vs baseline: 1.1990x; 1.1219x over previous
#include <cuda_runtime.h>
#include <cuda_bf16.h>
#include <cuda_fp16.h>
#include <math.h>
#include <stdint.h>

#define D_MODEL 256
#define NHEAD   8
#define HEAD_DIM 32
#define B_SZ    4
#define N_SZ    256

// ---------------- device scratch ----------------
__device__ float g_Wt[D_MODEL * D_MODEL];
__device__ float g_node_p[B_SZ * N_SZ * D_MODEL];
__device__ float g_out0[B_SZ * N_SZ * D_MODEL];
// W fp16: 8 K-chunks of [256 n][32 k] fp16, 64B rows, SW64 swizzle (16KB/chunk)
__device__ __align__(128) unsigned char g_WF[131072];

__device__ __forceinline__ uint32_t smem_u32(const void* p) {
    uint32_t a;
    asm("{ .reg .u64 t; cvta.to.shared.u64 t, %1; cvt.u32.u64 %0, t; }" : "=r"(a) : "l"(p));
    return a;
}

__device__ __forceinline__ void ldsm_x4(uint32_t r[4], uint32_t addr) {
    asm volatile("ldmatrix.sync.aligned.m8n8.x4.shared.b16 {%0,%1,%2,%3}, [%4];"
                 : "=r"(r[0]), "=r"(r[1]), "=r"(r[2]), "=r"(r[3]) : "r"(addr));
}

__device__ __forceinline__ void mma_f16(float c[4], const uint32_t a[4], const uint32_t b[2]) {
    asm volatile(
        "mma.sync.aligned.m16n8k16.row.col.f32.f16.f16.f32 "
        "{%0,%1,%2,%3}, {%4,%5,%6,%7}, {%8,%9}, {%0,%1,%2,%3};"
        : "+f"(c[0]), "+f"(c[1]), "+f"(c[2]), "+f"(c[3])
        : "r"(a[0]), "r"(a[1]), "r"(a[2]), "r"(a[3]), "r"(b[0]), "r"(b[1]));
}

#define MBAR_INIT(mbar, cnt) \
    asm volatile("mbarrier.init.shared.b64 [%0], %1;" :: "r"((uint32_t)(mbar)), "r"((uint32_t)(cnt)) : "memory")
#define MBAR_EXPECT_TX(mbar, tx) \
    asm volatile("mbarrier.arrive.expect_tx.shared.b64 _, [%0], %1;" :: "r"((uint32_t)(mbar)), "r"((uint32_t)(tx)) : "memory")
#define MBAR_WAIT(mbar, parity) do {                                          \
    uint32_t _m = (uint32_t)(mbar); uint32_t _p = (uint32_t)(parity);         \
    asm volatile(                                                             \
        "{\n\t.reg .pred P1;\n\t"                                             \
        "WAIT_LOOP_%=:\n\t"                                                   \
        "mbarrier.try_wait.parity.acquire.cta.shared::cta.b64 P1, [%0], %1, 0x989680;\n\t" \
        "@P1 bra.uni WAIT_DONE_%=;\n\t"                                       \
        "bra.uni WAIT_LOOP_%=;\n\t"                                           \
        "WAIT_DONE_%=:\n\t}"                                                  \
        :: "r"(_m), "r"(_p) : "memory");                                      \
} while (0)
#define BULK_G2S(dst, src, bytes, mbar) \
    asm volatile("cp.async.bulk.shared::cta.global.mbarrier::complete_tx::bytes [%0], [%1], %2, [%3];" \
                 :: "r"((uint32_t)(dst)), "l"(src), "r"((uint32_t)(bytes)), "r"((uint32_t)(mbar)) : "memory")

// ---------------- prep kernels ----------------
__global__ void transpose_kernel(const float* __restrict__ W) {
    int o = blockIdx.x * 256 + threadIdx.x;  // o = k*256 + d
    int k = o >> 8, d = o & 255;
    g_Wt[o] = W[d * 256 + k];
}

// 8 chunks of [256 n][32 k] fp16, 64B rows, SW64
__global__ void wprep_kernel(const float* __restrict__ W) {
    int idx = blockIdx.x * 256 + threadIdx.x;  // d*256 + k
    int d = idx >> 8, k = idx & 255;
    float w = W[idx];
    __half h = __float2half_rn(w);
    int chunk = k >> 5, kc = k & 31;
    int off = d * 64 + kc * 2;
    int sw = off ^ ((off >> 3) & 0x30);      // SW64
    int pos = chunk * 16384 + sw;
    *(unsigned short*)(g_WF + pos) = __half_as_ushort(h);
}

// ---------------- high-occupancy projections (R12 exact) ----------------
__global__ void __launch_bounds__(256, 6)
proj_nodes_simple(const float* __restrict__ A, const float* __restrict__ bias) {
    __shared__ float As[4][256];
    const int tid = threadIdx.x;
    const int r0 = blockIdx.x * 4;

#pragma unroll
    for (int q = 0; q < 4; q++)
        As[q][tid] = A[(size_t)(r0 + q) * 256 + tid];
    __syncthreads();

    float a0 = 0.0f, a1 = 0.0f, a2 = 0.0f, a3 = 0.0f;
#pragma unroll 8
    for (int k = 0; k < 256; k++) {
        float wv = g_Wt[k * 256 + tid];
        a0 = fmaf(As[0][k], wv, a0);
        a1 = fmaf(As[1][k], wv, a1);
        a2 = fmaf(As[2][k], wv, a2);
        a3 = fmaf(As[3][k], wv, a3);
    }
    float bv = bias[tid];
    g_node_p[(size_t)(r0 + 0) * 256 + tid] = a0 + bv;
    g_node_p[(size_t)(r0 + 1) * 256 + tid] = a1 + bv;
    g_node_p[(size_t)(r0 + 2) * 256 + tid] = a2 + bv;
    g_node_p[(size_t)(r0 + 3) * 256 + tid] = a3 + bv;
}

__global__ void __launch_bounds__(256, 6)
proj_final_simple(const float* __restrict__ bias, float* __restrict__ C) {
    __shared__ float As[4][256];
    const int tid = threadIdx.x;
    const int r0 = blockIdx.x * 4;

#pragma unroll
    for (int q = 0; q < 4; q++)
        As[q][tid] = g_out0[(size_t)(r0 + q) * 256 + tid];
    __syncthreads();

    float a0 = 0.0f, a1 = 0.0f, a2 = 0.0f, a3 = 0.0f;
#pragma unroll 8
    for (int k = 0; k < 256; k++) {
        float wv = g_Wt[k * 256 + tid];
        a0 = fmaf(As[0][k], wv, a0);
        a1 = fmaf(As[1][k], wv, a1);
        a2 = fmaf(As[2][k], wv, a2);
        a3 = fmaf(As[3][k], wv, a3);
    }
    float bv = bias[tid];
    C[(size_t)(r0 + 0) * 256 + tid] = a0 + bv;
    C[(size_t)(r0 + 1) * 256 + tid] = a1 + bv;
    C[(size_t)(r0 + 2) * 256 + tid] = a2 + bv;
    C[(size_t)(r0 + 3) * 256 + tid] = a3 + bv;
}

// ---------------- edge projection + scores: fp16 2-pass (A split, W single) ----------------
// SMEM: A slots: 2 x (4KB hi + 4KB lo)  @ 0      (16KB)
//       W slots: 2 x 16KB fp16          @ 16384  (32KB)
// SM_DYN kept at 80KB (epilogue npj staging needs 66.5KB); 2 CTAs/SM.
#define SM_A   0
#define SM_W   16384
#define SM_DYN 81920
#define NTHR   256

// convert one float4 of A-chunk data -> fp16 hi + fp16 lo, SW64 store
__device__ __forceinline__ void cvt_store_a(char* sm, int slot, int flat, float4 v) {
    __half hx = __float2half_rn(v.x);
    __half hy = __float2half_rn(v.y);
    __half hz = __float2half_rn(v.z);
    __half hw = __float2half_rn(v.w);
    __half lx = __float2half_rn(v.x - __half2float(hx));
    __half ly = __float2half_rn(v.y - __half2float(hy));
    __half lz = __float2half_rn(v.z - __half2float(hz));
    __half lw = __float2half_rn(v.w - __half2float(hw));
    uint2 hi2, lo2;
    hi2.x = (uint32_t)__half_as_ushort(hx) | ((uint32_t)__half_as_ushort(hy) << 16);
    hi2.y = (uint32_t)__half_as_ushort(hz) | ((uint32_t)__half_as_ushort(hw) << 16);
    lo2.x = (uint32_t)__half_as_ushort(lx) | ((uint32_t)__half_as_ushort(ly) << 16);
    lo2.y = (uint32_t)__half_as_ushort(lz) | ((uint32_t)__half_as_ushort(lw) << 16);
    int row = flat >> 3, c4 = flat & 7;      // 8 float4 per 32-k row
    int off = row * 64 + c4 * 8;
    int sw = off ^ ((off >> 3) & 0x30);      // SW64
    char* base = sm + SM_A + slot * 8192;
    *(uint2*)(base + sw) = hi2;
    *(uint2*)(base + 4096 + sw) = lo2;
}

__global__ void __launch_bounds__(NTHR, 2)
edge_score_mma(const float* __restrict__ edges, const float* __restrict__ bias,
               float* __restrict__ scores) {
    extern __shared__ char sm[];
    __shared__ __align__(8) unsigned long long mbarr[2];
    const uint32_t smb = smem_u32(sm);
    const uint32_t mb0 = smem_u32(&mbarr[0]);
    const int tid = threadIdx.x, wid = tid >> 5, lane = tid & 31;
    const int jt = blockIdx.x, i = blockIdx.y, b = blockIdx.z;
    const int wm = (wid >> 2) * 32;
    const int wn = (wid & 3) * 64;

    const float* A = edges + ((((size_t)b * N_SZ + i) * N_SZ) + (size_t)jt * 64) * D_MODEL;
    const unsigned long long gwf = (unsigned long long)__cvta_generic_to_global(g_WF);

    if (tid == 0) { MBAR_INIT(mb0, 1); MBAR_INIT(mb0 + 8, 1); }
    __syncthreads();

    if (tid == 0) {
        MBAR_EXPECT_TX(mb0, 16384);
        BULK_G2S(smb + SM_W, gwf, 16384, mb0);
    }
#pragma unroll
    for (int q = 0; q < 2; q++) {
        int flat = q * NTHR + tid;
        float4 v = *(const float4*)(A + (size_t)(flat >> 3) * 256 + (flat & 7) * 4);
        cvt_store_a(sm, 0, flat, v);
    }
    __syncthreads();

    float acc[2][8][4];
#pragma unroll
    for (int mf = 0; mf < 2; mf++)
#pragma unroll
        for (int nf = 0; nf < 8; nf++)
#pragma unroll
            for (int c = 0; c < 4; c++) acc[mf][nf][c] = 0.0f;

    uint32_t apre[2], axor[2];
#pragma unroll
    for (int mf = 0; mf < 2; mf++) {
        int row = wm + mf * 16 + (lane & 15);
        apre[mf] = row * 64;
        axor[mf] = (row & 6) << 3;           // SW64
    }
    const int koffA = (lane >> 4) * 8;
    uint32_t bpre[4], bxor[4];
#pragma unroll
    for (int gb = 0; gb < 4; gb++) {
        int n = wn + gb * 16 + (((lane >> 3) >= 2) ? 8 : 0) + (lane & 7);
        bpre[gb] = n * 64;
        bxor[gb] = (n & 6) << 3;             // SW64
    }
    const int kcB = ((lane >> 3) & 1) * 8;

#pragma unroll 1
    for (int ch = 0; ch < 8; ch++) {
        const int cur = ch & 1, nxt = cur ^ 1;
        if (ch < 7 && tid == 0) {
            MBAR_EXPECT_TX(mb0 + 8 * nxt, 16384);
            BULK_G2S(smb + SM_W + nxt * 16384, gwf + (ch + 1) * 16384, 16384, mb0 + 8 * nxt);
        }
        MBAR_WAIT(mb0 + 8 * cur, (ch >> 1) & 1);

        const uint32_t abase = smb + SM_A + cur * 8192;
        const uint32_t wbase = smb + SM_W + cur * 16384;

#pragma unroll
        for (int ks = 0; ks < 2; ks++) {
            float4 v0;
            int f0 = ks * NTHR + tid;
            if (ch < 7)
                v0 = *(const float4*)(A + (ch + 1) * 32 + (size_t)(f0 >> 3) * 256 + (f0 & 7) * 4);

            const uint32_t kg2 = (uint32_t)((ks * 16 + koffA) * 2);
            const uint32_t kc2 = (uint32_t)((ks * 16 + kcB) * 2);

            // W fragments (held across both passes)
            uint32_t bw[4][4];
#pragma unroll
            for (int gb = 0; gb < 4; gb++)
                ldsm_x4(bw[gb], wbase + bpre[gb] + (kc2 ^ bxor[gb]));
            // A fragments hi + lo
            uint32_t ah[2][4], al[2][4];
#pragma unroll
            for (int mf = 0; mf < 2; mf++) {
                uint32_t ad = abase + apre[mf] + (kg2 ^ axor[mf]);
                ldsm_x4(ah[mf], ad);
                ldsm_x4(al[mf], ad + 4096);
            }

            // pass 1: ah x W — 16 independent acc chains
#pragma unroll
            for (int gb = 0; gb < 4; gb++)
#pragma unroll
                for (int mf = 0; mf < 2; mf++)
#pragma unroll
                    for (int s2 = 0; s2 < 2; s2++)
                        mma_f16(acc[mf][gb * 2 + s2], ah[mf], &bw[gb][s2 * 2]);
            // pass 2: al x W
#pragma unroll
            for (int gb = 0; gb < 4; gb++)
#pragma unroll
                for (int mf = 0; mf < 2; mf++)
#pragma unroll
                    for (int s2 = 0; s2 < 2; s2++)
                        mma_f16(acc[mf][gb * 2 + s2], al[mf], &bw[gb][s2 * 2]);

            if (ch < 7) cvt_store_a(sm, nxt, f0, v0);
        }
        __syncthreads();
    }

    // ---- epilogue (R13 exact) ----
    {
        float* nps = (float*)sm;
        const float* src = g_node_p + ((size_t)b * N_SZ + jt * 64) * 256;
        int row = tid >> 2, q4 = tid & 3;
        const float4* s4 = (const float4*)(src + (size_t)row * 256) + q4 * 16;
        float4* d4 = (float4*)(nps + row * 260) + q4 * 16;
#pragma unroll
        for (int q = 0; q < 16; q++) d4[q] = s4[q];
    }
    __syncthreads();

    float pb[16], p1[16];
    {
        const float* npi = g_node_p + ((size_t)b * N_SZ + i) * 256;
#pragma unroll
        for (int h = 0; h < 2; h++)
#pragma unroll
            for (int nf = 0; nf < 4; nf++)
#pragma unroll
                for (int v2 = 0; v2 < 2; v2++) {
                    int idx = h * 8 + nf * 2 + v2;
                    int d = wn + (h * 4 + nf) * 8 + (lane & 3) * 2 + v2;
                    float bv = bias[d];
                    pb[idx] = bv;
                    p1[idx] = bv + npi[d];
                }
    }

    const float* nps = (const float*)sm;
#pragma unroll
    for (int mf = 0; mf < 2; mf++) {
#pragma unroll
        for (int half = 0; half < 2; half++) {
            int r = wm + mf * 16 + (lane >> 2) + half * 8;
            const float* nj = nps + r * 260 + wn;
#pragma unroll
            for (int h = 0; h < 2; h++) {
                float s = 0.0f;
#pragma unroll
                for (int nf = 0; nf < 4; nf++)
#pragma unroll
                    for (int v2 = 0; v2 < 2; v2++) {
                        int idx = h * 8 + nf * 2 + v2;
                        float a = acc[mf][h * 4 + nf][half * 2 + v2];
                        float njv = nj[(h * 4 + nf) * 8 + (lane & 3) * 2 + v2];
                        s += (a + p1[idx]) * (a + pb[idx] + njv);
                    }
                s += __shfl_xor_sync(0xffffffffu, s, 1);
                s += __shfl_xor_sync(0xffffffffu, s, 2);
                if ((lane & 3) == 0) {
                    int hg = (wn >> 5) + h;
                    scores[((((size_t)b * NHEAD + hg) * N_SZ + i) << 8) + jt * 64 + r] =
                        10.0f * tanhf(s * 0.17677669529663687f);
                }
            }
        }
    }
}

// ---------------- softmax + AV v2 (R15 exact) ----------------
#define SAV_SMEM 65536
__global__ void __launch_bounds__(256, 2)
softmax_av2(float* __restrict__ attn) {
    extern __shared__ char savsm[];
    float* V = (float*)savsm;            // [256 j][32 d]
    float* P = V + 256 * 32;             // [32 r][256 j]

    const int i0 = blockIdx.x * 32, h = blockIdx.y, b = blockIdx.z;
    const int tid = threadIdx.x, wid = tid >> 5, lane = tid & 31;

    {
        const float* npb = g_node_p + (size_t)b * N_SZ * D_MODEL + h * 32;
#pragma unroll
        for (int q = 0; q < 8; q++) {
            int flat = q * 256 + tid;
            int j = flat >> 3, f4 = flat & 7;
            *(float4*)&V[j * 32 + f4 * 4] = *(const float4*)(npb + (size_t)j * 256 + f4 * 4);
        }
    }

#pragma unroll
    for (int q = 0; q < 4; q++) {
        int r = wid + q * 8;
        float* srow = attn + ((((size_t)(b * NHEAD + h) * N_SZ) + i0 + r) << 8);
        float4 x0 = *(const float4*)(srow + lane * 8);
        float4 x1 = *(const float4*)(srow + lane * 8 + 4);
        float m = fmaxf(fmaxf(fmaxf(x0.x, x0.y), fmaxf(x0.z, x0.w)),
                        fmaxf(fmaxf(x1.x, x1.y), fmaxf(x1.z, x1.w)));
#pragma unroll
        for (int off = 16; off > 0; off >>= 1)
            m = fmaxf(m, __shfl_xor_sync(0xffffffffu, m, off));
        float e0 = __expf(x0.x - m), e1 = __expf(x0.y - m), e2 = __expf(x0.z - m), e3 = __expf(x0.w - m);
        float e4 = __expf(x1.x - m), e5 = __expf(x1.y - m), e6 = __expf(x1.z - m), e7 = __expf(x1.w - m);
        float t = e0 + e1 + e2 + e3 + e4 + e5 + e6 + e7;
#pragma unroll
        for (int off = 16; off > 0; off >>= 1)
            t += __shfl_xor_sync(0xffffffffu, t, off);
        float inv = 1.0f / t;
        float4 p0 = make_float4(e0 * inv, e1 * inv, e2 * inv, e3 * inv);
        float4 p1 = make_float4(e4 * inv, e5 * inv, e6 * inv, e7 * inv);
        *(float4*)&P[r * 256 + lane * 8] = p0;
        *(float4*)&P[r * 256 + lane * 8 + 4] = p1;
        *(float4*)(srow + lane * 8) = p0;
        *(float4*)(srow + lane * 8 + 4) = p1;
    }
    __syncthreads();

    const int d = lane;
    float a0 = 0.0f, a1 = 0.0f, a2 = 0.0f, a3 = 0.0f;
    const float* Prow0 = &P[wid * 256];
#pragma unroll 4
    for (int j = 0; j < 256; j++) {
        float vv = V[j * 32 + d];
        a0 = fmaf(Prow0[j], vv, a0);
        a1 = fmaf(Prow0[j + 8 * 256], vv, a1);
        a2 = fmaf(Prow0[j + 16 * 256], vv, a2);
        a3 = fmaf(Prow0[j + 24 * 256], vv, a3);
    }
    float* ob = g_out0 + ((size_t)(b * N_SZ + i0)) * D_MODEL + h * 32 + d;
    ob[(size_t)(wid + 0) * 256] = a0;
    ob[(size_t)(wid + 8) * 256] = a1;
    ob[(size_t)(wid + 16) * 256] = a2;
    ob[(size_t)(wid + 24) * 256] = a3;
}

// ---------------- launch ----------------
extern "C" void kernel_launch(void* const* d_in, const int* in_sizes, int n_in,
                              void* d_out, int out_size) {
    const float* nodes = (const float*)d_in[0];
    const float* edges = (const float*)d_in[1];
    const float* W     = (const float*)d_in[2];
    const float* bias  = (const float*)d_in[3];

    float* out  = (float*)d_out;
    float* attn = out + B_SZ * N_SZ * D_MODEL;

    cudaFuncSetAttribute(edge_score_mma, cudaFuncAttributeMaxDynamicSharedMemorySize, SM_DYN);
    cudaFuncSetAttribute(softmax_av2, cudaFuncAttributeMaxDynamicSharedMemorySize, SAV_SMEM);

    transpose_kernel<<<256, 256>>>(W);                          // 0
    wprep_kernel<<<256, 256>>>(W);                              // 1
    proj_nodes_simple<<<256, 256>>>(nodes, bias);               // 2
    dim3 g2(4, N_SZ, B_SZ);
    edge_score_mma<<<g2, NTHR, SM_DYN>>>(edges, bias, attn);    // 3 (profiled)
    dim3 g3(N_SZ / 32, NHEAD, B_SZ);
    softmax_av2<<<g3, 256, SAV_SMEM>>>(attn);                   // 4
    proj_final_simple<<<256, 256>>>(bias, out);                 // 5
}